// round 1
// baseline (speedup 1.0000x reference)
#include <cuda_runtime.h>
#include <cuda_bf16.h>
#include <math.h>

#define N_ATOMS 10000
#define E_TILE  32

// Output region bases (flattened tuple):
//  l=0: (10000,1,20,4)  base 0        per-atom 80
//  l=1: (10000,3,18,4)  base 800000   per-atom 216
//  l=2: (10000,5,16,4)  base 2960000  per-atom 320
//  l=3: (10000,7,14,4)  base 6160000  per-atom 392

__device__ int g_rowptr[N_ATOMS + 1];

__global__ void rowptr_kernel(const int* __restrict__ I, int nE) {
    int a = blockIdx.x * blockDim.x + threadIdx.x;
    if (a > N_ATOMS) return;
    int lo = 0, hi = nE;
    while (lo < hi) {
        int mid = (lo + hi) >> 1;
        if (I[mid] < a) lo = mid + 1; else hi = mid;
    }
    g_rowptr[a] = lo;
}

__global__ __launch_bounds__(256, 6)
void expand_kernel(const float* __restrict__ R,
                   const int*   __restrict__ J,
                   const int*   __restrict__ species,
                   const float* __restrict__ embed,
                   float*       __restrict__ out)
{
    // per-edge staging: rad[20] | ang[16] | sp[4]  (sp 16B-aligned: 40-word stride)
    __shared__ float sh[E_TILE][40];
    __shared__ int s_range[2];

    const int t    = threadIdx.x;
    const int atom = blockIdx.x;

    if (t < 2) s_range[t] = g_rowptr[atom + t];

    // ---- decode this thread's output element (q = flat (l,m,n) index, c vectorized) ----
    int n, am, outOff;
    {
        int q = t;
        if (q < 20)       { n = q;                             am = 20;               outOff = atom * 80  + q * 4; }
        else if (q < 74)  { int qq = q - 20;  n = qq % 18;     am = 21 + qq / 18;     outOff = 800000  + atom * 216 + qq * 4; }
        else if (q < 154) { int qq = q - 74;  n = qq % 16;     am = 24 + qq / 16;     outOff = 2960000 + atom * 320 + qq * 4; }
        else              { int qq = q - 154; n = qq % 14;     am = 29 + qq / 14;     outOff = 6160000 + atom * 392 + qq * 4; }
    }

    __syncthreads();
    const int s0 = s_range[0];
    const int s1 = s_range[1];

    float ax = 0.f, ay = 0.f, az = 0.f, aw = 0.f;

    for (int base = s0; base < s1; base += E_TILE) {
        const int E = min(E_TILE, s1 - base);

        if (t < E) {
            const int e = base + t;
            const float x = R[3 * e + 0];
            const float y = R[3 * e + 1];
            const float z = R[3 * e + 2];
            const float r   = sqrtf(x * x + y * y + z * z);
            const float inv = 1.0f / (r + 1e-12f);
            const float ux = x * inv, uy = y * inv, uz = z * inv;

            const float rc = fminf(r, 5.0f);
            const float fc = 0.5f * (__cosf(0.6283185307179586f * rc) + 1.0f);

            // radial: sin(k*pi/5*r)*fc, k=1..20 via Chebyshev recurrence
            float s1v, c1;
            __sincosf(0.6283185307179586f * r, &s1v, &c1);
            const float c2 = 2.0f * c1;
            float* row = sh[t];
            float sm2 = 0.0f, sm1 = s1v;
            row[0] = s1v * fc;
            #pragma unroll
            for (int k = 1; k < 20; k++) {
                const float sk = c2 * sm1 - sm2;
                sm2 = sm1; sm1 = sk;
                row[k] = sk * fc;
            }

            // angular (real spherical harmonics, reference ordering)
            const float x2 = ux * ux, y2 = uy * uy, z2 = uz * uz;
            row[20] = 0.28209479177387814f;
            row[21] = 0.4886025119029199f * uy;
            row[22] = 0.4886025119029199f * uz;
            row[23] = 0.4886025119029199f * ux;
            row[24] = 1.0925484305920792f * ux * uy;
            row[25] = 1.0925484305920792f * uy * uz;
            row[26] = 0.31539156525252005f * (3.0f * z2 - 1.0f);
            row[27] = 1.0925484305920792f * ux * uz;
            row[28] = 0.5462742152960396f * (x2 - y2);
            row[29] = 0.5900435899266435f * uy * (3.0f * x2 - y2);
            row[30] = 2.890611442640554f * ux * uy * uz;
            row[31] = 0.4570457994644658f * uy * (5.0f * z2 - 1.0f);
            row[32] = 0.3731763325901154f * uz * (5.0f * z2 - 3.0f);
            row[33] = 0.4570457994644658f * ux * (5.0f * z2 - 1.0f);
            row[34] = 1.445305721320277f  * uz * (x2 - y2);
            row[35] = 0.5900435899266435f * ux * (x2 - 3.0f * y2);

            // species embedding gather (rows are 16B -> float4)
            const int sp = species[J[e]];
            const float4 sv = *reinterpret_cast<const float4*>(embed + 4 * sp);
            *reinterpret_cast<float4*>(row + 36) = sv;
        }
        __syncthreads();

        #pragma unroll 4
        for (int e = 0; e < E; e++) {
            const float rv = sh[e][n] * sh[e][am];
            const float4 sv = *reinterpret_cast<const float4*>(&sh[e][36]);
            ax = fmaf(rv, sv.x, ax);
            ay = fmaf(rv, sv.y, ay);
            az = fmaf(rv, sv.z, az);
            aw = fmaf(rv, sv.w, aw);
        }
        __syncthreads();
    }

    if (t < 252) {
        float4 o; o.x = ax; o.y = ay; o.z = az; o.w = aw;
        *reinterpret_cast<float4*>(out + outOff) = o;
    }
}

extern "C" void kernel_launch(void* const* d_in, const int* in_sizes, int n_in,
                              void* d_out, int out_size)
{
    const float* R       = (const float*)d_in[0];
    const int*   I       = (const int*)  d_in[1];
    const int*   J       = (const int*)  d_in[2];
    const int*   species = (const int*)  d_in[3];
    const float* embed   = (const float*)d_in[4];
    float* out = (float*)d_out;
    const int nE = in_sizes[1];

    rowptr_kernel<<<(N_ATOMS + 1 + 255) / 256, 256>>>(I, nE);
    expand_kernel<<<N_ATOMS, 256>>>(R, J, species, embed, out);
}